// round 5
// baseline (speedup 1.0000x reference)
#include <cuda_runtime.h>

#define BB    512
#define VV    50257
#define TT    2048
#define TOPK  50
#define NT    256
#define NW    8
#define CAP   3072
#define CAP2  1024
#define MASKP 1600

typedef unsigned long long u64;

struct Scr {
    float sval[TOPK];
    int   sidx[TOPK];
    float wred[NW];
    u64   gkey[2];
    unsigned runKey;
    float Z, M0, Zk, invt;
    int   ncand, nc2, fb, m;
};

__device__ __forceinline__ unsigned fkey(float x) {
    unsigned u = __float_as_uint(x);
    return (u & 0x80000000u) ? ~u : (u | 0x80000000u);
}
__device__ __forceinline__ float fdec(unsigned k) {
    return __uint_as_float((k & 0x80000000u) ? (k ^ 0x80000000u) : ~k);
}
__device__ __forceinline__ void penal4(float4& X, unsigned bits, float rp, float invrp) {
    if (bits & 1u) X.x = X.x < 0.f ? X.x * rp : X.x * invrp;
    if (bits & 2u) X.y = X.y < 0.f ? X.y * rp : X.y * invrp;
    if (bits & 4u) X.z = X.z < 0.f ? X.z * rp : X.z * invrp;
    if (bits & 8u) X.w = X.w < 0.f ? X.w * rp : X.w * invrp;
}
__device__ __forceinline__ void pushc(u64* ck, int* pnc, float x, int v) {
    int pos = atomicAdd(pnc, 1);
    if (pos < CAP)
        ck[pos] = ((u64)fkey(x) << 32) | (u64)(0xFFFFFFFFu - (unsigned)v);
}

__global__ void __launch_bounds__(NT)
decode_kernel(const float* __restrict__ logits,
              const int*   __restrict__ prev,
              const float* __restrict__ randu,
              const float* __restrict__ tempp,
              const float* __restrict__ toppp,
              const float* __restrict__ rpp,
              float*  probsF, double* probsD,
              long long* idx64, float* idxF, double* idxD)
{
    __shared__ unsigned mask[MASKP];
    __shared__ u64 ckey[CAP];
    __shared__ u64 ckey2[CAP2];
    __shared__ Scr S;

    const int b    = blockIdx.x;
    const int tid  = threadIdx.x;
    const int lane = tid & 31;
    const int wrp  = tid >> 5;

    const int p     = (4 - (b & 3)) & 3;       // align row to float4
    const int nvec  = (VV - p) >> 2;
    const int vtail = p + (nvec << 2);

    const float* lrow  = logits + (long long)b * VV;
    float*  orowF = probsF ? probsF + (long long)b * VV : nullptr;
    double* orowD = probsD ? probsD + (long long)b * VV : nullptr;

    if (orowD) {                                // rare layout: scalar zero-fill
        for (int v = tid; v < VV; v += NT) orowD[v] = 0.0;
    }

    for (int i = tid; i < MASKP; i += NT) mask[i] = 0u;
    if (tid == 0) { S.runKey = 0u; S.ncand = 0; S.nc2 = 0; S.fb = 0; }
    __syncthreads();

    // ---- penalty bitmask ----
    const int* prow = prev + (long long)b * TT;
    for (int i = tid; i < TT; i += NT) {
        unsigned tok = (unsigned)prow[i];
        if (tok < (unsigned)VV)
            atomicOr(&mask[tok >> 5], 1u << (tok & 31));
    }
    __syncthreads();

    const float rp    = __ldg(rpp);
    const float invrp = 1.f / rp;
    volatile unsigned* rkp = &S.runKey;

    // ---- seed running max with first group (1024 elements) ----
    float4 X0; int v00 = p + 4 * tid;
    const bool have0 = tid < nvec;
    if (have0) {
        X0 = __ldg((const float4*)(lrow + v00));
        unsigned bits = __funnelshift_r(mask[v00 >> 5], mask[(v00 >> 5) + 1], v00 & 31) & 0xFu;
        if (bits) penal4(X0, bits, rp, invrp);
        float gm = fmaxf(fmaxf(X0.x, X0.y), fmaxf(X0.z, X0.w));
        atomicMax(&S.runKey, fkey(gm));
    }
    __syncthreads();

    // ---- THE single full pass: zero-store + Z + running-max + candidate push ----
    float zs = 0.f;
    if (have0) {
        if (orowF) *(float4*)(orowF + v00) = make_float4(0.f, 0.f, 0.f, 0.f);
        zs += __expf(X0.x) + __expf(X0.y) + __expf(X0.z) + __expf(X0.w);
        float t = fdec(*rkp) - 10.f;
        if (X0.x >= t) pushc(ckey, &S.ncand, X0.x, v00);
        if (X0.y >= t) pushc(ckey, &S.ncand, X0.y, v00 + 1);
        if (X0.z >= t) pushc(ckey, &S.ncand, X0.z, v00 + 2);
        if (X0.w >= t) pushc(ckey, &S.ncand, X0.w, v00 + 3);
    }
    #pragma unroll 2
    for (int k = tid + NT; k < nvec; k += NT) {
        const int v0 = p + 4 * k;
        float4 X = __ldg((const float4*)(lrow + v0));
        unsigned bits = __funnelshift_r(mask[v0 >> 5], mask[(v0 >> 5) + 1], v0 & 31) & 0xFu;
        if (bits) penal4(X, bits, rp, invrp);
        if (orowF) *(float4*)(orowF + v0) = make_float4(0.f, 0.f, 0.f, 0.f);
        zs += __expf(X.x) + __expf(X.y) + __expf(X.z) + __expf(X.w);
        float gm = fmaxf(fmaxf(X.x, X.y), fmaxf(X.z, X.w));
        unsigned rk = *rkp;
        unsigned gk = fkey(gm);
        if (gk > rk) { atomicMax(&S.runKey, gk); rk = gk; }
        float t = fdec(rk) - 10.f;
        if (X.x >= t) pushc(ckey, &S.ncand, X.x, v0);
        if (X.y >= t) pushc(ckey, &S.ncand, X.y, v0 + 1);
        if (X.z >= t) pushc(ckey, &S.ncand, X.z, v0 + 2);
        if (X.w >= t) pushc(ckey, &S.ncand, X.w, v0 + 3);
    }
    // scalar tails (prefix + remainder)
    for (int v = tid; v < p; v += NT) {
        float x = __ldg(lrow + v);
        if ((mask[v >> 5] >> (v & 31)) & 1u) x = x < 0.f ? x * rp : x * invrp;
        if (orowF) orowF[v] = 0.f;
        zs += __expf(x);
        float t = fdec(*rkp) - 10.f;
        if (x >= t) pushc(ckey, &S.ncand, x, v);
    }
    for (int v = vtail + tid; v < VV; v += NT) {
        float x = __ldg(lrow + v);
        if ((mask[v >> 5] >> (v & 31)) & 1u) x = x < 0.f ? x * rp : x * invrp;
        if (orowF) orowF[v] = 0.f;
        zs += __expf(x);
        float t = fdec(*rkp) - 10.f;
        if (x >= t) pushc(ckey, &S.ncand, x, v);
    }

    // ---- reduce Z ----
    #pragma unroll
    for (int off = 16; off; off >>= 1)
        zs += __shfl_xor_sync(0xffffffffu, zs, off);
    if (lane == 0) S.wred[wrp] = zs;
    __syncthreads();
    if (tid == 0) {
        float gz = 0.f;
        #pragma unroll
        for (int j = 0; j < NW; j++) gz += S.wred[j];
        S.Z = gz;
    }
    __syncthreads();

    const float M = fdec(S.runKey);       // exact max over vector region (superset-safe)
    int ncand = S.ncand;

    // ---- choose candidate set: compact (x >= M-9) or fallback regather ----
    u64* cptr = ckey2;
    int  n    = 0;

    if (ncand > CAP) {
        if (tid == 0) S.fb = 1;           // pushes were dropped -> set incomplete
    } else {
        const unsigned tk = fkey(M - 9.f);
        for (int i = tid; i < ncand; i += NT) {
            u64 c = ckey[i];
            if ((unsigned)(c >> 32) >= tk) {
                int q = atomicAdd(&S.nc2, 1);
                if (q < CAP2) ckey2[q] = c;
            }
        }
        __syncthreads();
        int nc2 = S.nc2;
        if (nc2 >= TOPK && nc2 <= CAP2) {
            n = nc2;
        } else if (nc2 > CAP2) {
            cptr = ckey; n = ncand;        // complete superset, just bigger sweep
        } else {
            // widen to M-10 (ckey provably complete down to M-10)
            __syncthreads();
            if (tid == 0) S.nc2 = 0;
            __syncthreads();
            const unsigned tk2 = fkey(M - 10.f);
            for (int i = tid; i < ncand; i += NT) {
                u64 c = ckey[i];
                if ((unsigned)(c >> 32) >= tk2) {
                    int q = atomicAdd(&S.nc2, 1);
                    if (q < CAP2) ckey2[q] = c;
                }
            }
            __syncthreads();
            nc2 = S.nc2;
            if (nc2 >= 1 && nc2 <= CAP2 && (nc2 >= TOPK || nc2 == ncand)) n = nc2;
            else if (tid == 0) S.fb = 1;
        }
    }
    __syncthreads();

    if (S.fb) {   // rare: exact adaptive regather from gmem (L2-hot)
        float delta = 9.f;
        for (int it = 0; it < 8; ++it) {
            __syncthreads();
            if (tid == 0) S.ncand = 0;
            __syncthreads();
            const float t = M - delta;
            for (int k = tid; k < nvec; k += NT) {
                const int v0 = p + 4 * k;
                float4 X = __ldg((const float4*)(lrow + v0));
                unsigned bits = __funnelshift_r(mask[v0 >> 5], mask[(v0 >> 5) + 1], v0 & 31) & 0xFu;
                if (bits) penal4(X, bits, rp, invrp);
                if (X.x >= t) pushc(ckey, &S.ncand, X.x, v0);
                if (X.y >= t) pushc(ckey, &S.ncand, X.y, v0 + 1);
                if (X.z >= t) pushc(ckey, &S.ncand, X.z, v0 + 2);
                if (X.w >= t) pushc(ckey, &S.ncand, X.w, v0 + 3);
            }
            for (int v = tid; v < p; v += NT) {
                float x = __ldg(lrow + v);
                if ((mask[v >> 5] >> (v & 31)) & 1u) x = x < 0.f ? x * rp : x * invrp;
                if (x >= t) pushc(ckey, &S.ncand, x, v);
            }
            for (int v = vtail + tid; v < VV; v += NT) {
                float x = __ldg(lrow + v);
                if ((mask[v >> 5] >> (v & 31)) & 1u) x = x < 0.f ? x * rp : x * invrp;
                if (x >= t) pushc(ckey, &S.ncand, x, v);
            }
            __syncthreads();
            int nc = S.ncand;
            if (nc >= TOPK && nc <= CAP) break;
            delta = (nc < TOPK) ? delta * 2.f : delta * 0.5f;
        }
        cptr = ckey; n = min(S.ncand, CAP);
    }

    const int kk = min(TOPK, n);

    // ---- warp 0: exact top-kk (value desc, index asc) ----
    if (tid < 32) {
        for (int k = 0; k < kk; ++k) {
            u64 best = 0ull;
            for (int i = tid; i < n; i += 32) {
                u64 c = cptr[i];
                if (c > best) best = c;
            }
            #pragma unroll
            for (int off = 16; off; off >>= 1) {
                u64 o = __shfl_xor_sync(0xffffffffu, best, off);
                if (o > best) best = o;
            }
            for (int i = tid; i < n; i += 32)
                if (cptr[i] == best) cptr[i] = 0ull;
            if (tid == 0) {
                S.sval[k] = fdec((unsigned)(best >> 32));
                S.sidx[k] = (int)(0xFFFFFFFFu - (unsigned)(best & 0xFFFFFFFFull));
            }
            __syncwarp();
        }
    }
    __syncthreads();

    // ---- thread 0: top-p cutoff, Zk ----
    if (tid == 0) {
        const float Z    = S.Z;
        const float topp = __ldg(toppp);
        const float temp = fmaxf(__ldg(tempp), 1e-5f);
        const float invt = 1.f / temp;

        float c = 0.f; int cnt = 0;
        for (int k = 0; k < kk; ++k) {
            c += expf(S.sval[k]) / Z;          // == exp(sval-M)/Z_ref
            if (c <= topp) cnt++; else break;
        }
        int mm = cnt < 1 ? 1 : cnt;
        if (mm > kk) mm = kk;

        const float M0 = S.sval[0];
        float Zk = 0.f;
        for (int k = 0; k < mm; ++k) Zk += expf((S.sval[k] - M0) * invt);

        S.m = mm; S.M0 = M0; S.Zk = Zk; S.invt = invt;
        S.gkey[0] = 0ull; S.gkey[1] = 0ull;
    }
    __syncthreads();

    // ---- parallel Gumbel argmax over kept tokens ----
    const int   mm   = S.m;
    const float M0   = S.M0;
    const float Zk   = S.Zk;
    const float invt = S.invt;

    if (tid < 64) {
        u64 key = 0ull;
        if (tid < mm) {
            float pk = expf((S.sval[tid] - M0) * invt) / Zk;
            float u  = __ldg(randu + (long long)b * VV + S.sidx[tid]);
            float r  = pk / (-logf(u));
            key = ((u64)fkey(r) << 32) |
                  (u64)(0xFFFFFFFFu - (unsigned)S.sidx[tid]);
        }
        #pragma unroll
        for (int off = 16; off; off >>= 1) {
            u64 o = __shfl_xor_sync(0xffffffffu, key, off);
            if (o > key) key = o;
        }
        if (lane == 0) S.gkey[wrp] = key;
    }
    __syncthreads();

    if (tid == 0) {
        u64 best = S.gkey[0] > S.gkey[1] ? S.gkey[0] : S.gkey[1];
        int besti = (int)(0xFFFFFFFFu - (unsigned)(best & 0xFFFFFFFFull));
        if (idx64) idx64[b] = (long long)besti;
        if (idxF)  idxF[b]  = (float)besti;
        if (idxD)  idxD[b]  = (double)besti;
    }

    // ---- scatter the mm nonzero probabilities ----
    if (tid < mm) {
        float pk = expf((S.sval[tid] - M0) * invt) / Zk;
        if (orowF) orowF[S.sidx[tid]] = pk;
        else if (orowD) orowD[S.sidx[tid]] = (double)pk;
    }
}

extern "C" void kernel_launch(void* const* d_in, const int* in_sizes, int n_in,
                              void* d_out, int out_size)
{
    const float* logits = (const float*)d_in[0];
    const int*   prev   = (const int*)d_in[1];
    const float* randu  = (const float*)d_in[2];
    const float* temp   = (const float*)d_in[3];
    const float* topp   = (const float*)d_in[4];
    const float* rp     = (const float*)d_in[5];

    float*  probsF = nullptr; double* probsD = nullptr;
    long long* idx64 = nullptr; float* idxF = nullptr; double* idxD = nullptr;

    const long long BV = (long long)BB * VV;
    const long long oz = (long long)out_size;

    if (oz == BB + BV) {
        // tuple concat, float32 elements (idx cast to float) — the passing layout
        idxF = (float*)d_out; probsF = (float*)d_out + BB;
    } else if (oz == 2 * BB + BV) {
        idx64 = (long long*)d_out; probsF = (float*)d_out + 2 * BB;
    } else if (oz == BB + BV / 2) {
        idx64 = (long long*)d_out; probsF = (float*)((long long*)d_out + BB);
    } else if (oz == BV) {
        probsF = (float*)d_out;
    } else if (oz == BB) {
        idx64 = (long long*)d_out;
    } else if (oz == 8LL * BB + 4LL * BV) {
        idx64 = (long long*)d_out; probsF = (float*)((char*)d_out + 8LL * BB);
    } else {
        idxF = (float*)d_out; probsF = (float*)d_out + BB;
    }

    decode_kernel<<<BB, NT>>>(logits, prev, randu, temp, topp, rp,
                              probsF, probsD, idx64, idxF, idxD);
}